// round 11
// baseline (speedup 1.0000x reference)
#include <cuda_runtime.h>
#include <math_constants.h>

// Problem dims
#define BATCH 64
#define DIM   768
#define MEM   2048
#define NCLS  1000

#define EC    48               // e-chunk per score block (DIM/EC = 16)
#define NEC   16
#define KCG   48               // gemm k-chunk
#define NKC   16               // DIM/KCG partials
#define NJT   12               // gemm j-tiles of 64
#define GEMM_BLOCKS (NJT * NKC)        // 192
#define ZERO_BLOCKS 32

// Role layout (producers first -> guaranteed in wave 1 of 1184 resident CTAs)
#define G1_END  GEMM_BLOCKS                  // 192  : gemm1 (q partials)
#define Z_END   (G1_END + ZERO_BLOCKS)       // 224  : zero g_scores
#define G2_END  (Z_END + GEMM_BLOCKS)        // 416  : gemm2 (t partials)
#define SCORE_BLOCKS 2048
#define GRIDN   (G2_END + SCORE_BLOCKS)      // 2464

// Counter protocol: producers P arrive after fence; each consumer, after its
// wait passes, arrives once too -> per-launch quantum Q = P + C is exact, so
// base = (v/Q)*Q is correct for any mid-launch read (v - base <= Q-1 always).
#define P1 224
#define Q1 416      // 224 producers (gemm1+zero) + 192 consumers (gemm2)
#define P2 192
#define Q2 2240     // 192 producers (gemm2) + 2048 consumers (score)

// Scratch (allocation-free). Partials written by plain stores -> no zeroing.
__device__ float g_qp[NKC * BATCH * DIM];   // 3 MB q split-K partials
__device__ float g_tp[NKC * BATCH * DIM];   // 3 MB t split-K partials
__device__ float g_scores[BATCH * MEM];
__device__ unsigned g_ctr1, g_ctr2;         // monotonic, never reset
__device__ unsigned g_rowdone[BATCH];       // monotonic, 32 arrivals/row/launch

// ---------------------------------------------------------------------------
// Producer arrival: every thread fences its stores, block syncs, thread 0
// bumps the counter. Consumer wait: poll until base+P arrivals of this
// launch, then arrive (completes the quantum) and fence-acquire.
// ---------------------------------------------------------------------------
__device__ __forceinline__ void producer_arrive(unsigned* ctr) {
    __threadfence();
    __syncthreads();
    if (threadIdx.x == 0) atomicAdd(ctr, 1u);
}

__device__ __forceinline__ void consumer_wait(unsigned* ctr, unsigned prod,
                                              unsigned quantum) {
    if (threadIdx.x == 0) {
        const unsigned v0 = *(volatile unsigned*)ctr;
        const unsigned base = (v0 / quantum) * quantum;
        while (*(volatile unsigned*)ctr < base + prod) __nanosleep(64);
        __threadfence();
        atomicAdd(ctr, 1u);    // consumer arrival keeps quantum deterministic
    }
    __syncthreads();
}

// ---------------------------------------------------------------------------
// GEMM role: partial[kc][b][j] = sum_{d in chunk kc} A[b,d]*W[d,j].
// 192 units = 12 j-tiles(64) x 16 k-chunks(48). Thread: 4 j x 4 b = 16 accs.
// stage0: A = x directly. stage1: A[b,d] = sum_p g_qp[p][b][d] (L2).
// ---------------------------------------------------------------------------
__device__ void gemm_role(const float* __restrict__ x,
                          const float* __restrict__ W,
                          float* __restrict__ outp, int stage, int u) {
    const int jt = u % NJT;
    const int kc = u / NJT;
    const int k0 = kc * KCG;

    __shared__ float xs[KCG][BATCH + 1];

    for (int i = threadIdx.x; i < BATCH * KCG; i += 256) {
        const int b = i / KCG;
        const int d = i - b * KCG;
        if (stage == 0) {
            xs[d][b] = x[b * DIM + k0 + d];
        } else {
            float s = 0.0f;
            #pragma unroll
            for (int p = 0; p < NKC; p++)
                s += __ldcg(&g_qp[((size_t)p * BATCH + b) * DIM + k0 + d]);
            xs[d][b] = s;
        }
    }
    __syncthreads();

    const int jv = threadIdx.x & 15;
    const int bg = threadIdx.x >> 4;
    const int j  = jt * 64 + jv * 4;

    float acc[4][4];
    #pragma unroll
    for (int bb = 0; bb < 4; bb++)
        #pragma unroll
        for (int jj = 0; jj < 4; jj++) acc[bb][jj] = 0.0f;

    #pragma unroll 4
    for (int d = 0; d < KCG; d++) {
        const float4 w = *(const float4*)&W[(size_t)(k0 + d) * DIM + j];
        #pragma unroll
        for (int bb = 0; bb < 4; bb++) {
            const float xv = xs[d][bg * 4 + bb];
            acc[bb][0] = fmaf(xv, w.x, acc[bb][0]);
            acc[bb][1] = fmaf(xv, w.y, acc[bb][1]);
            acc[bb][2] = fmaf(xv, w.z, acc[bb][2]);
            acc[bb][3] = fmaf(xv, w.w, acc[bb][3]);
        }
    }

    #pragma unroll
    for (int bb = 0; bb < 4; bb++) {
        const int b = bg * 4 + bb;
        *(float4*)&outp[((size_t)kc * BATCH + b) * DIM + j] =
            make_float4(acc[bb][0], acc[bb][1], acc[bb][2], acc[bb][3]);
    }
}

// ---------------------------------------------------------------------------
// Epilogue (run by the 32nd-finishing score block of each batch row):
// leaky-relu(g_scores[b,:]) scattered into shared logits[1000], softmax, out.
// ---------------------------------------------------------------------------
__device__ void epilogue_row(int b, const int* __restrict__ lab32,
                             float* __restrict__ out) {
    const int tid = threadIdx.x;
    __shared__ float logits[NCLS];
    __shared__ float red[8];
    __shared__ int   sh_is64;

    for (int i = tid; i < NCLS; i += 256) logits[i] = 0.0f;
    if (tid == 0) {
        int any = 0;
        #pragma unroll
        for (int k = 0; k < 32; k++) any |= lab32[2 * k + 1];
        sh_is64 = (any == 0) ? 1 : 0;  // int64 labels in [0,1000): odd words 0
    }
    __syncthreads();
    const int is64 = sh_is64;

    for (int i = tid; i < MEM; i += 256) {
        const size_t idx = (size_t)b * MEM + i;
        const float s = __ldcg(&g_scores[idx]);
        const float sv = (s >= 0.0f) ? s : 0.01f * s;
        int lab = is64 ? lab32[2 * idx] : lab32[idx];
        lab = min(max(lab, 0), NCLS - 1);
        atomicAdd(&logits[lab], sv);
    }
    __syncthreads();

    // --- max ---
    float mx = -CUDART_INF_F;
    for (int i = tid; i < NCLS; i += 256) mx = fmaxf(mx, logits[i]);
    #pragma unroll
    for (int o = 16; o > 0; o >>= 1) mx = fmaxf(mx, __shfl_xor_sync(0xffffffffu, mx, o));
    if ((tid & 31) == 0) red[tid >> 5] = mx;
    __syncthreads();
    if (tid < 32) {
        float v = (tid < 8) ? red[tid] : -CUDART_INF_F;
        #pragma unroll
        for (int o = 4; o > 0; o >>= 1) v = fmaxf(v, __shfl_xor_sync(0xffffffffu, v, o));
        if (tid == 0) red[0] = v;
    }
    __syncthreads();
    mx = red[0];
    __syncthreads();

    // --- exp + sum ---
    float sum = 0.0f;
    for (int i = tid; i < NCLS; i += 256) {
        const float e = __expf(logits[i] - mx);
        logits[i] = e;
        sum += e;
    }
    #pragma unroll
    for (int o = 16; o > 0; o >>= 1) sum += __shfl_xor_sync(0xffffffffu, sum, o);
    if ((tid & 31) == 0) red[tid >> 5] = sum;
    __syncthreads();
    if (tid < 32) {
        float v = (tid < 8) ? red[tid] : 0.0f;
        #pragma unroll
        for (int o = 4; o > 0; o >>= 1) v += __shfl_xor_sync(0xffffffffu, v, o);
        if (tid == 0) red[0] = v;
    }
    __syncthreads();
    const float inv = 1.0f / red[0];

    for (int i = tid; i < NCLS; i += 256) out[b * NCLS + i] = logits[i] * inv;
}

// ---------------------------------------------------------------------------
// ONE kernel, role-specialized blocks:
//   [0,192)    gemm1: q partials = x @ W_K chunk          -> arrive ctr1
//   [192,224)  zero g_scores                              -> arrive ctr1
//   [224,416)  gemm2: wait ctr1; t partials = q @ W_Q     -> arrive ctr2
//   [416,2464) score: wait ctr2; stream mem (proven loop); row ticket;
//              32nd block per row runs the fused epilogue.
// ---------------------------------------------------------------------------
__global__ void __launch_bounds__(256, 8) fused_all(
    const float* __restrict__ x, const float* __restrict__ mem,
    const int* __restrict__ lab32,
    const float* __restrict__ W_Q, const float* __restrict__ W_K,
    float* __restrict__ out)
{
    const int bid = blockIdx.x;

    if (bid < G1_END) {                       // gemm1
        gemm_role(x, W_K, g_qp, 0, bid);
        producer_arrive(&g_ctr1);
        return;
    }
    if (bid < Z_END) {                        // zero g_scores
        const int zi = (bid - G1_END) * 256 + threadIdx.x;
        const float4 z = make_float4(0.f, 0.f, 0.f, 0.f);
        for (int k = zi; k < BATCH * MEM / 4; k += ZERO_BLOCKS * 256)
            ((float4*)g_scores)[k] = z;
        producer_arrive(&g_ctr1);
        return;
    }
    if (bid < G2_END) {                       // gemm2
        consumer_wait(&g_ctr1, P1, Q1);
        gemm_role(nullptr, W_Q, g_tp, 1, bid - Z_END);
        producer_arrive(&g_ctr2);
        return;
    }

    // ---- score role (proven streaming config, unchanged) ----
    const int s  = bid - G2_END;              // 0..2047
    const int b  = s & 63;
    const int e0 = ((s >> 6) & 15) * EC;
    const int m  = (s >> 10) * 1024 + threadIdx.x * 4;
    const float4* mp = (const float4*)(mem + (size_t)b * DIM * MEM
                                           + (size_t)e0 * MEM + m);

    consumer_wait(&g_ctr2, P2, Q2);

    __shared__ float ts[EC];
    if (threadIdx.x < EC) {
        float v = 0.0f;
        #pragma unroll
        for (int p = 0; p < NKC; p++)
            v += __ldcg(&g_tp[((size_t)p * BATCH + b) * DIM + e0 + threadIdx.x]);
        ts[threadIdx.x] = v;
    }
    __syncthreads();

    float ax = 0.f, ay = 0.f, az = 0.f, aw = 0.f;
    #pragma unroll 8
    for (int e = 0; e < EC; e++) {
        const float4 v = __ldcs(&mp[(size_t)e * (MEM / 4)]);
        const float w = ts[e];  // warp-uniform broadcast
        ax = fmaf(w, v.x, ax);
        ay = fmaf(w, v.y, ay);
        az = fmaf(w, v.z, az);
        aw = fmaf(w, v.w, aw);
    }

    float* sp = &g_scores[b * MEM + m];
    atomicAdd(sp + 0, ax);
    atomicAdd(sp + 1, ay);
    atomicAdd(sp + 2, az);
    atomicAdd(sp + 3, aw);

    // ---- row completion ticket: 32nd block of row b runs the epilogue ----
    __threadfence();
    __syncthreads();
    __shared__ int winner;
    if (threadIdx.x == 0) {
        const unsigned t = atomicAdd(&g_rowdone[b], 1u);
        winner = ((t & 31u) == 31u) ? 1 : 0;
    }
    __syncthreads();
    if (winner) epilogue_row(b, lab32, out);
}

// ---------------------------------------------------------------------------
// Launch: ONE node. Inputs mapped by element count: x 49152, mem 100663296,
// labels 131072, W_Q / W_K 589824 each (W_Q first). Output: f32[64,1000].
// ---------------------------------------------------------------------------
extern "C" void kernel_launch(void* const* d_in, const int* in_sizes, int n_in,
                              void* d_out, int out_size) {
    const float* x   = nullptr;
    const float* mem = nullptr;
    const int* labs  = nullptr;
    const float* W_Q = nullptr;
    const float* W_K = nullptr;

    for (int i = 0; i < n_in; i++) {
        const int sz = in_sizes[i];
        if (sz == BATCH * DIM)            x    = (const float*)d_in[i];
        else if (sz == BATCH * DIM * MEM) mem  = (const float*)d_in[i];
        else if (sz == BATCH * MEM)       labs = (const int*)d_in[i];
        else if (sz == DIM * DIM) {
            if (!W_Q) W_Q = (const float*)d_in[i];
            else      W_K = (const float*)d_in[i];
        }
    }
    float* out = (float*)d_out;

    fused_all<<<GRIDN, 256>>>(x, mem, labs, W_Q, W_K, out);
}

// round 12
// speedup vs baseline: 1.3698x; 1.3698x over previous
#include <cuda_runtime.h>
#include <math_constants.h>

// Problem dims
#define BATCH 64
#define DIM   768
#define MEM   2048
#define NCLS  1000

#define EC  48                 // e-chunk per score block (DIM/EC = 16)
#define NEC (DIM / EC)
#define KC  16                 // gemm k-chunk

// Contiguous scratch: [q | t | scores], zeroed by ONE memset node per launch.
#define QOFF 0
#define TOFF (BATCH * DIM)
#define SOFF (2 * BATCH * DIM)
#define SCRATCH_FLOATS (2 * BATCH * DIM + BATCH * MEM)
__device__ float g_scratch[SCRATCH_FLOATS];

// ---------------------------------------------------------------------------
// GEMM stage: C[64,768] += A[64,768] @ W[768,768]  (row-major, split-K)
// grid = (6 j-tiles of 128, 48 k-chunks of 16), block = 256 threads.
// Thread: 4 consecutive j (float4 W load) x 8 b (smem broadcast), 8x W reuse.
// stage 0: A = x,         C = q  (W = W_K)
// stage 1: A = q (PDL-sync first), C = t  (W = W_Q)
// ---------------------------------------------------------------------------
__global__ void __launch_bounds__(256) gemm_stage(const float* __restrict__ Aext,
                                                  const float* __restrict__ W,
                                                  int stage) {
    if (stage != 0) cudaGridDependencySynchronize();  // q complete

    const float* A = (stage == 0) ? Aext : &g_scratch[QOFF];
    float* Cc      = (stage == 0) ? &g_scratch[QOFF] : &g_scratch[TOFF];

    __shared__ float xs[KC][BATCH + 1];

    const int k0 = blockIdx.y * KC;

    for (int i = threadIdx.x; i < BATCH * KC; i += 256) {
        int b = i >> 4;          // i / 16
        int d = i & (KC - 1);    // i % 16
        xs[d][b] = A[b * DIM + k0 + d];
    }
    __syncthreads();

    const int jv = threadIdx.x & 31;
    const int bg = threadIdx.x >> 5;
    const int j  = blockIdx.x * 128 + jv * 4;

    float acc[8][4];
    #pragma unroll
    for (int bb = 0; bb < 8; bb++)
        #pragma unroll
        for (int jj = 0; jj < 4; jj++) acc[bb][jj] = 0.0f;

    #pragma unroll
    for (int d = 0; d < KC; d++) {
        const float4 w = *(const float4*)&W[(size_t)(k0 + d) * DIM + j];
        #pragma unroll
        for (int bb = 0; bb < 8; bb++) {
            const float xv = xs[d][bg * 8 + bb];
            acc[bb][0] = fmaf(xv, w.x, acc[bb][0]);
            acc[bb][1] = fmaf(xv, w.y, acc[bb][1]);
            acc[bb][2] = fmaf(xv, w.z, acc[bb][2]);
            acc[bb][3] = fmaf(xv, w.w, acc[bb][3]);
        }
    }

    #pragma unroll
    for (int bb = 0; bb < 8; bb++) {
        const int b = bg * 8 + bb;
        atomicAdd(&Cc[b * DIM + j + 0], acc[bb][0]);
        atomicAdd(&Cc[b * DIM + j + 1], acc[bb][1]);
        atomicAdd(&Cc[b * DIM + j + 2], acc[bb][2]);
        atomicAdd(&Cc[b * DIM + j + 3], acc[bb][3]);
    }
    cudaTriggerProgrammaticLaunchCompletion();
}

// ---------------------------------------------------------------------------
// Dominant kernel (proven ~62.4us / ~82% DRAM config, unchanged):
// scores[b,m] += sum_{e in chunk} t[b,e]*mem[b,e,m]. Streams 402 MB once.
// grid = (2, 16, 64) = 2048 blocks x 256 threads, regs<=32 -> 8 CTAs/SM.
// ---------------------------------------------------------------------------
__global__ void __launch_bounds__(256) score_partial(const float* __restrict__ mem) {
    const int b  = blockIdx.z;
    const int e0 = blockIdx.y * EC;
    const int m  = blockIdx.x * 1024 + threadIdx.x * 4;
    const float4* mp = (const float4*)(mem + (size_t)b * DIM * MEM
                                           + (size_t)e0 * MEM + m);

    cudaGridDependencySynchronize();   // t + zeroed scores complete

    __shared__ float ts[EC];
    if (threadIdx.x < EC) ts[threadIdx.x] = g_scratch[TOFF + b * DIM + e0 + threadIdx.x];
    __syncthreads();

    float ax = 0.f, ay = 0.f, az = 0.f, aw = 0.f;
    #pragma unroll 8
    for (int e = 0; e < EC; e++) {
        const float4 v = __ldcs(&mp[(size_t)e * (MEM / 4)]);
        const float w = ts[e];  // warp-uniform broadcast
        ax = fmaf(w, v.x, ax);
        ay = fmaf(w, v.y, ay);
        az = fmaf(w, v.z, az);
        aw = fmaf(w, v.w, aw);
    }

    float* sp = &g_scratch[SOFF + b * MEM + m];
    atomicAdd(sp + 0, ax);
    atomicAdd(sp + 1, ay);
    atomicAdd(sp + 2, az);
    atomicAdd(sp + 3, aw);
    cudaTriggerProgrammaticLaunchCompletion();
}

// ---------------------------------------------------------------------------
// Fused epilogue: leaky-relu(scores) scattered into shared logits[1000]
// (smem atomics), softmax, write out. 64 blocks x 512 threads.
// PDL: logits zero + label-dtype detect pre-sync (overlaps score tail).
// Label dtype: int64 labels in [0,1000) have all-zero odd 32-bit words.
// ---------------------------------------------------------------------------
__global__ void __launch_bounds__(512) epilogue(const int* __restrict__ lab32,
                                                float* __restrict__ out) {
    const int b = blockIdx.x;
    const int tid = threadIdx.x;

    __shared__ float logits[NCLS];
    __shared__ float red[16];
    __shared__ int   sh_is64;

    for (int i = tid; i < NCLS; i += 512) logits[i] = 0.0f;
    if (tid == 0) {
        int any = 0;
        #pragma unroll
        for (int k = 0; k < 32; k++) any |= lab32[2 * k + 1];
        sh_is64 = (any == 0) ? 1 : 0;
    }
    __syncthreads();
    const int is64 = sh_is64;

    cudaGridDependencySynchronize();   // scores complete

    for (int i = tid; i < MEM; i += 512) {
        const size_t idx = (size_t)b * MEM + i;
        const float s = g_scratch[SOFF + idx];
        const float sv = (s >= 0.0f) ? s : 0.01f * s;
        int lab = is64 ? lab32[2 * idx] : lab32[idx];
        lab = min(max(lab, 0), NCLS - 1);
        atomicAdd(&logits[lab], sv);
    }
    __syncthreads();

    // --- max ---
    float mx = -CUDART_INF_F;
    for (int i = tid; i < NCLS; i += 512) mx = fmaxf(mx, logits[i]);
    #pragma unroll
    for (int o = 16; o > 0; o >>= 1) mx = fmaxf(mx, __shfl_xor_sync(0xffffffffu, mx, o));
    if ((tid & 31) == 0) red[tid >> 5] = mx;
    __syncthreads();
    if (tid < 32) {
        float v = (tid < 16) ? red[tid] : -CUDART_INF_F;
        #pragma unroll
        for (int o = 8; o > 0; o >>= 1) v = fmaxf(v, __shfl_xor_sync(0xffffffffu, v, o));
        if (tid == 0) red[0] = v;
    }
    __syncthreads();
    mx = red[0];
    __syncthreads();

    // --- exp + sum ---
    float sum = 0.0f;
    for (int i = tid; i < NCLS; i += 512) {
        const float e = __expf(logits[i] - mx);
        logits[i] = e;
        sum += e;
    }
    #pragma unroll
    for (int o = 16; o > 0; o >>= 1) sum += __shfl_xor_sync(0xffffffffu, sum, o);
    if ((tid & 31) == 0) red[tid >> 5] = sum;
    __syncthreads();
    if (tid < 32) {
        float v = (tid < 16) ? red[tid] : 0.0f;
        #pragma unroll
        for (int o = 8; o > 0; o >>= 1) v += __shfl_xor_sync(0xffffffffu, v, o);
        if (tid == 0) red[0] = v;
    }
    __syncthreads();
    const float inv = 1.0f / red[0];

    for (int i = tid; i < NCLS; i += 512) out[b * NCLS + i] = logits[i] * inv;
}

// ---------------------------------------------------------------------------
// Launch: memset(scratch) -> gemm1 -> gemm2 (PDL) -> score (PDL) ->
// epilogue (PDL). Inputs mapped by element count: x 49152, mem 100663296,
// labels 131072, W_Q / W_K 589824 each (W_Q first). Output: f32[64,1000].
// ---------------------------------------------------------------------------
template <typename... Args>
static inline void launch_pdl(void (*kern)(Args...), dim3 grid, dim3 block,
                              Args... args) {
    cudaLaunchConfig_t cfg = {};
    cfg.gridDim = grid;
    cfg.blockDim = block;
    cfg.dynamicSmemBytes = 0;
    cfg.stream = 0;
    cudaLaunchAttribute attr[1];
    attr[0].id = cudaLaunchAttributeProgrammaticStreamSerialization;
    attr[0].val.programmaticStreamSerializationAllowed = 1;
    cfg.attrs = attr;
    cfg.numAttrs = 1;
    cudaLaunchKernelEx(&cfg, kern, args...);
}

extern "C" void kernel_launch(void* const* d_in, const int* in_sizes, int n_in,
                              void* d_out, int out_size) {
    const float* x   = nullptr;
    const float* mem = nullptr;
    const int* labs  = nullptr;
    const float* W_Q = nullptr;
    const float* W_K = nullptr;

    for (int i = 0; i < n_in; i++) {
        const int sz = in_sizes[i];
        if (sz == BATCH * DIM)            x    = (const float*)d_in[i];
        else if (sz == BATCH * DIM * MEM) mem  = (const float*)d_in[i];
        else if (sz == BATCH * MEM)       labs = (const int*)d_in[i];
        else if (sz == DIM * DIM) {
            if (!W_Q) W_Q = (const float*)d_in[i];
            else      W_K = (const float*)d_in[i];
        }
    }
    float* out = (float*)d_out;

    // One memset node zeroes q, t and scores (all atomic accumulation targets).
    void* scratch_ptr = nullptr;
    cudaGetSymbolAddress(&scratch_ptr, g_scratch);
    cudaMemsetAsync(scratch_ptr, 0, SCRATCH_FLOATS * sizeof(float), 0);

    gemm_stage<<<dim3(DIM / 128, DIM / KC), 256>>>(x, W_K, 0);   // q = x @ W_K
    launch_pdl(gemm_stage, dim3(DIM / 128, DIM / KC), dim3(256), x, W_Q, 1);
    launch_pdl(score_partial, dim3(2, NEC, BATCH), dim3(256), mem);
    launch_pdl(epilogue, dim3(BATCH), dim3(512), labs, out);
}

// round 13
// speedup vs baseline: 1.3987x; 1.0211x over previous
#include <cuda_runtime.h>
#include <math_constants.h>

// Problem dims
#define BATCH 64
#define DIM   768
#define MEM   2048
#define NCLS  1000

#define EC  48                 // e-chunk per score block (DIM/EC = 16)
#define NEC (DIM / EC)
#define KC  16                 // gemm k-chunk

// Scratch (allocation-free)
__device__ float g_q[BATCH * DIM];
__device__ float g_t[BATCH * DIM];
__device__ float g_scores[BATCH * MEM];

// ---------------------------------------------------------------------------
// Zero scratch: g_q, g_t (GEMM atomic targets) and g_scores (score atomics).
// 57344 float4 stores -> 112 blocks x 512 threads.
// ---------------------------------------------------------------------------
__global__ void zero_scratch() {
    const int i = blockIdx.x * 512 + threadIdx.x;
    const float4 z = make_float4(0.f, 0.f, 0.f, 0.f);
    if (i < BATCH * DIM / 4) {
        ((float4*)g_q)[i] = z;
        ((float4*)g_t)[i] = z;
    }
    if (i < BATCH * MEM / 4) ((float4*)g_scores)[i] = z;
    cudaTriggerProgrammaticLaunchCompletion();
}

// ---------------------------------------------------------------------------
// GEMM stage: C[64,768] += A[64,768] @ W[768,768]  (row-major, split-K)
// grid = (6 j-tiles of 128, 48 k-chunks of 16), block = 256 threads.
// Thread: 4 consecutive j (float4 W load) x 8 b (smem broadcast), 8x W reuse.
// PDL: stage 0 syncs right before its atomics (compute overlaps zero kernel);
// stage 1 reads g_q so it syncs up front.
// ---------------------------------------------------------------------------
__global__ void __launch_bounds__(256) gemm_stage(const float* __restrict__ Aext,
                                                  const float* __restrict__ W,
                                                  int stage) {
    if (stage != 0) cudaGridDependencySynchronize();  // wait for g_q

    const float* A = (stage == 0) ? Aext : g_q;
    float* Cc      = (stage == 0) ? g_q  : g_t;

    __shared__ float xs[KC][BATCH + 1];

    const int k0 = blockIdx.y * KC;

    for (int i = threadIdx.x; i < BATCH * KC; i += 256) {
        int b = i >> 4;          // i / 16
        int d = i & (KC - 1);    // i % 16
        xs[d][b] = A[b * DIM + k0 + d];
    }
    __syncthreads();

    const int jv = threadIdx.x & 31;
    const int bg = threadIdx.x >> 5;
    const int j  = blockIdx.x * 128 + jv * 4;

    float acc[8][4];
    #pragma unroll
    for (int bb = 0; bb < 8; bb++)
        #pragma unroll
        for (int jj = 0; jj < 4; jj++) acc[bb][jj] = 0.0f;

    #pragma unroll
    for (int d = 0; d < KC; d++) {
        const float4 w = *(const float4*)&W[(size_t)(k0 + d) * DIM + j];
        #pragma unroll
        for (int bb = 0; bb < 8; bb++) {
            const float xv = xs[d][bg * 8 + bb];
            acc[bb][0] = fmaf(xv, w.x, acc[bb][0]);
            acc[bb][1] = fmaf(xv, w.y, acc[bb][1]);
            acc[bb][2] = fmaf(xv, w.z, acc[bb][2]);
            acc[bb][3] = fmaf(xv, w.w, acc[bb][3]);
        }
    }

    if (stage == 0) cudaGridDependencySynchronize();  // zero of g_q must be done

    #pragma unroll
    for (int bb = 0; bb < 8; bb++) {
        const int b = bg * 8 + bb;
        atomicAdd(&Cc[b * DIM + j + 0], acc[bb][0]);
        atomicAdd(&Cc[b * DIM + j + 1], acc[bb][1]);
        atomicAdd(&Cc[b * DIM + j + 2], acc[bb][2]);
        atomicAdd(&Cc[b * DIM + j + 3], acc[bb][3]);
    }
    cudaTriggerProgrammaticLaunchCompletion();
}

// ---------------------------------------------------------------------------
// Dominant kernel: scores[b,m] += sum_{e in chunk} t[b,e]*mem[b,e,m].
// Streams 402 MB of mem exactly once (HBM-bound).
// grid = (2, 16, 64) = 2048 blocks x 256 threads, regs<=32 -> 8 CTAs/SM.
// ONLY change vs the proven 63.8us config: unroll 8 -> 16 (deeper MLP window;
// 16 independent LDG.128s in flight between accumulator-dependency stalls).
// ---------------------------------------------------------------------------
__global__ void __launch_bounds__(256) score_partial(const float* __restrict__ mem) {
    const int b  = blockIdx.z;
    const int e0 = blockIdx.y * EC;
    const int m  = blockIdx.x * 1024 + threadIdx.x * 4;
    const float4* mp = (const float4*)(mem + (size_t)b * DIM * MEM
                                           + (size_t)e0 * MEM + m);

    cudaGridDependencySynchronize();   // g_t + zeroed g_scores ready

    __shared__ float ts[EC];
    if (threadIdx.x < EC) ts[threadIdx.x] = g_t[b * DIM + e0 + threadIdx.x];
    __syncthreads();

    float ax = 0.f, ay = 0.f, az = 0.f, aw = 0.f;
    #pragma unroll 16
    for (int e = 0; e < EC; e++) {
        const float4 v = __ldcs(&mp[(size_t)e * (MEM / 4)]);
        const float w = ts[e];  // warp-uniform broadcast
        ax = fmaf(w, v.x, ax);
        ay = fmaf(w, v.y, ay);
        az = fmaf(w, v.z, az);
        aw = fmaf(w, v.w, aw);
    }

    float* sp = &g_scores[b * MEM + m];
    atomicAdd(sp + 0, ax);
    atomicAdd(sp + 1, ay);
    atomicAdd(sp + 2, az);
    atomicAdd(sp + 3, aw);
    cudaTriggerProgrammaticLaunchCompletion();
}

// ---------------------------------------------------------------------------
// Fused epilogue: leaky-relu(scores) scattered into shared logits[1000]
// (smem atomics), then softmax -> out[b, :]. 64 blocks x 512 threads.
// PDL: logits zero + label-dtype detect pre-sync (overlaps score tail).
// Label dtype: int64 labels in [0,1000) have all-zero odd 32-bit words.
// ---------------------------------------------------------------------------
__global__ void __launch_bounds__(512) epilogue(const int* __restrict__ lab32,
                                                float* __restrict__ out) {
    const int b = blockIdx.x;
    const int tid = threadIdx.x;

    __shared__ float logits[NCLS];
    __shared__ float red[16];
    __shared__ int   sh_is64;

    for (int i = tid; i < NCLS; i += 512) logits[i] = 0.0f;
    if (tid == 0) {
        int any = 0;
        #pragma unroll
        for (int k = 0; k < 32; k++) any |= lab32[2 * k + 1];
        sh_is64 = (any == 0) ? 1 : 0;
    }
    __syncthreads();
    const int is64 = sh_is64;

    cudaGridDependencySynchronize();   // g_scores complete

    for (int i = tid; i < MEM; i += 512) {
        const size_t idx = (size_t)b * MEM + i;
        const float s = g_scores[idx];
        const float sv = (s >= 0.0f) ? s : 0.01f * s;
        int lab = is64 ? lab32[2 * idx] : lab32[idx];
        lab = min(max(lab, 0), NCLS - 1);
        atomicAdd(&logits[lab], sv);
    }
    __syncthreads();

    // --- max ---
    float mx = -CUDART_INF_F;
    for (int i = tid; i < NCLS; i += 512) mx = fmaxf(mx, logits[i]);
    #pragma unroll
    for (int o = 16; o > 0; o >>= 1) mx = fmaxf(mx, __shfl_xor_sync(0xffffffffu, mx, o));
    if ((tid & 31) == 0) red[tid >> 5] = mx;
    __syncthreads();
    if (tid < 32) {
        float v = (tid < 16) ? red[tid] : -CUDART_INF_F;
        #pragma unroll
        for (int o = 8; o > 0; o >>= 1) v = fmaxf(v, __shfl_xor_sync(0xffffffffu, v, o));
        if (tid == 0) red[0] = v;
    }
    __syncthreads();
    mx = red[0];
    __syncthreads();

    // --- exp + sum ---
    float sum = 0.0f;
    for (int i = tid; i < NCLS; i += 512) {
        const float e = __expf(logits[i] - mx);
        logits[i] = e;
        sum += e;
    }
    #pragma unroll
    for (int o = 16; o > 0; o >>= 1) sum += __shfl_xor_sync(0xffffffffu, sum, o);
    if ((tid & 31) == 0) red[tid >> 5] = sum;
    __syncthreads();
    if (tid < 32) {
        float v = (tid < 16) ? red[tid] : 0.0f;
        #pragma unroll
        for (int o = 8; o > 0; o >>= 1) v += __shfl_xor_sync(0xffffffffu, v, o);
        if (tid == 0) red[0] = v;
    }
    __syncthreads();
    const float inv = 1.0f / red[0];

    for (int i = tid; i < NCLS; i += 512) out[b * NCLS + i] = logits[i] * inv;
}

// ---------------------------------------------------------------------------
// Launch chain with PDL on every edge (the proven 90.5us structure):
// zero -> gemm1 -> gemm2 -> score -> epilogue.
// Inputs mapped by element count: x 49152, mem 100663296, labels 131072,
// W_Q / W_K 589824 each (W_Q first).  Output: f32[64,1000].
// ---------------------------------------------------------------------------
template <typename... Args>
static inline void launch_pdl(void (*kern)(Args...), dim3 grid, dim3 block,
                              Args... args) {
    cudaLaunchConfig_t cfg = {};
    cfg.gridDim = grid;
    cfg.blockDim = block;
    cfg.dynamicSmemBytes = 0;
    cfg.stream = 0;
    cudaLaunchAttribute attr[1];
    attr[0].id = cudaLaunchAttributeProgrammaticStreamSerialization;
    attr[0].val.programmaticStreamSerializationAllowed = 1;
    cfg.attrs = attr;
    cfg.numAttrs = 1;
    cudaLaunchKernelEx(&cfg, kern, args...);
}

extern "C" void kernel_launch(void* const* d_in, const int* in_sizes, int n_in,
                              void* d_out, int out_size) {
    const float* x   = nullptr;
    const float* mem = nullptr;
    const int* labs  = nullptr;
    const float* W_Q = nullptr;
    const float* W_K = nullptr;

    for (int i = 0; i < n_in; i++) {
        const int sz = in_sizes[i];
        if (sz == BATCH * DIM)            x    = (const float*)d_in[i];
        else if (sz == BATCH * DIM * MEM) mem  = (const float*)d_in[i];
        else if (sz == BATCH * MEM)       labs = (const int*)d_in[i];
        else if (sz == DIM * DIM) {
            if (!W_Q) W_Q = (const float*)d_in[i];
            else      W_K = (const float*)d_in[i];
        }
    }
    float* out = (float*)d_out;

    zero_scratch<<<112, 512>>>();
    launch_pdl(gemm_stage, dim3(DIM / 128, DIM / KC), dim3(256), x, W_K, 0);
    launch_pdl(gemm_stage, dim3(DIM / 128, DIM / KC), dim3(256), x, W_Q, 1);
    launch_pdl(score_partial, dim3(2, NEC, BATCH), dim3(256), mem);
    launch_pdl(epilogue, dim3(BATCH), dim3(512), labs, out);
}